// round 6
// baseline (speedup 1.0000x reference)
#include <cuda_runtime.h>

// CNOT (13 qubits, control=wire0 -> bit12, target=wire1 -> bit11) as a pure
// row permutation of the state vector:
//   out[row, :] = x[row ^ ((row & 4096) >> 1), :]
// U (the huge input) is never read.
//
// Layout-adaptive: floats-per-row and total counts are derived at launch
// from in_sizes / out_size, treating every element as 4 bytes (the minimal
// interpretation). The kernel therefore never reads past in_sizes[x]*4 bytes
// or writes past out_size*4 bytes, regardless of how the harness lowered
// complex64.

static constexpr int D_ROWS = 8192;

__global__ void __launch_bounds__(256) cnot_permute(
    const float* __restrict__ x, float* __restrict__ out,
    int shift, int mask, int n)
{
    int idx = blockIdx.x * blockDim.x + threadIdx.x;
    if (idx >= n) return;
    int row = idx >> shift;                 // state row (0..8191)
    int off = idx & mask;                   // float within row
    int src = row ^ ((row & 4096) >> 1);    // CNOT involution
    out[idx] = x[(src << shift) | off];
}

__global__ void __launch_bounds__(256) cnot_permute_planar(
    const float* __restrict__ xr, const float* __restrict__ xi,
    float* __restrict__ out,
    int shift, int mask, int nplane)
{
    int idx = blockIdx.x * blockDim.x + threadIdx.x;
    if (idx >= nplane) return;
    int row = idx >> shift;
    int off = idx & mask;
    int s   = ((row ^ ((row & 4096) >> 1)) << shift) | off;
    out[idx]           = xr[s];
    out[idx + nplane]  = xi[s];
}

static inline int ilog2(int v) { int s = 0; while ((1 << s) < v) s++; return s; }

extern "C" void kernel_launch(void* const* d_in, const int* in_sizes, int n_in,
                              void* d_out, int out_size)
{
    float* out = (float*)d_out;
    constexpr int THREADS = 256;

    if (n_in <= 2) {
        // Single x buffer: the smaller of the (<=2) inputs. U is ~128x bigger.
        int xi = 0;
        if (n_in == 2 && in_sizes[1] < in_sizes[0]) xi = 1;
        const float* x = (const float*)d_in[xi];

        // Total floats to produce: bounded by BOTH out_size and x's size
        // (minimal 4B-per-element interpretation of each).
        int n = out_size < in_sizes[xi] ? out_size : in_sizes[xi];
        int fpr = n / D_ROWS;                 // floats per state-row
        if (fpr < 1) fpr = 1;
        int shift = ilog2(fpr);
        int mask  = (1 << shift) - 1;
        n = D_ROWS << shift;                  // exact multiple of rows

        int blocks = (n + THREADS - 1) / THREADS;
        cnot_permute<<<blocks, THREADS>>>(x, out, shift, mask, n);
    } else {
        // Planar real/imag: the two smallest inputs, original order kept.
        int a = 0, b = 1;
        if (in_sizes[b] < in_sizes[a]) { int t = a; a = b; b = t; }
        for (int i = 2; i < n_in; i++) {
            if (in_sizes[i] < in_sizes[a])      { b = a; a = i; }
            else if (in_sizes[i] < in_sizes[b]) { b = i; }
        }
        int re = a < b ? a : b;
        int im = a < b ? b : a;
        const float* xr  = (const float*)d_in[re];
        const float* xim = (const float*)d_in[im];

        int nplane = out_size / 2;
        if (in_sizes[re] < nplane) nplane = in_sizes[re];
        if (in_sizes[im] < nplane) nplane = in_sizes[im];
        int fpr = nplane / D_ROWS;
        if (fpr < 1) fpr = 1;
        int shift = ilog2(fpr);
        int mask  = (1 << shift) - 1;
        nplane = D_ROWS << shift;

        int blocks = (nplane + THREADS - 1) / THREADS;
        cnot_permute_planar<<<blocks, THREADS>>>(xr, xim, out, shift, mask, nplane);
    }
}

// round 10
// speedup vs baseline: 1.0386x; 1.0386x over previous
#include <cuda_runtime.h>
#include <cstdint>

// CNOT (13 qubits, control=wire0 -> bit12 of row, target=wire1 -> bit11) as
// a pure row permutation: out[row,:] = x[row ^ ((row&4096)>>1), :].
// U is never read.
//
// Empirically established (R6 pass, grid=2048, shift=6, rel_err=0):
//   x buffer = 524288 floats (64 floats per state row), out the same.
// The permutation swaps contiguous 2048-row chunks, so at flat float index
// granularity:  src = idx ^ ((idx & (4096<<shift)) >> 1)  — valid at any
// power-of-two granularity below one 2048-row chunk. float4 version:
// one XOR, one 16B load, one 16B store per thread; memcpy-grade coalescing.

__global__ void __launch_bounds__(256) cnot_perm_f4(
    const float4* __restrict__ x, float4* __restrict__ out,
    int swapbit, int n4)
{
    int idx = blockIdx.x * blockDim.x + threadIdx.x;
    if (idx >= n4) return;
    int src = idx ^ ((idx & swapbit) >> 1);
    out[idx] = x[src];
}

__global__ void __launch_bounds__(256) cnot_perm_f1(
    const float* __restrict__ x, float* __restrict__ out,
    int swapbit, int n)
{
    int idx = blockIdx.x * blockDim.x + threadIdx.x;
    if (idx >= n) return;
    int src = idx ^ ((idx & swapbit) >> 1);
    out[idx] = x[src];
}

static constexpr int D_ROWS = 8192;

static inline int ilog2i(int v) { int s = 0; while ((1 << s) < v) s++; return s; }

extern "C" void kernel_launch(void* const* d_in, const int* in_sizes, int n_in,
                              void* d_out, int out_size)
{
    // x = smallest input buffer (U is ~128x larger under any lowering).
    int xi = 0;
    for (int i = 1; i < n_in; i++)
        if (in_sizes[i] < in_sizes[xi]) xi = i;

    // Total floats: bounded by both out_size and x's element count (minimal
    // 4B-per-element interpretation — proven correct in R6).
    int n = out_size < in_sizes[xi] ? out_size : in_sizes[xi];
    int fpr = n / D_ROWS;            // floats per state-row (R6: 64)
    if (fpr < 1) fpr = 1;
    int shift = ilog2i(fpr);
    n = D_ROWS << shift;             // exact multiple of row count

    // Control bit 12 of the row index -> flat float-index bit (12 + shift).
    int swapbit_f = 4096 << shift;

    constexpr int THREADS = 256;
    const float* xf = (const float*)d_in[xi];
    float* outf = (float*)d_out;

    bool aligned16 = ((((uintptr_t)xf) | ((uintptr_t)outf)) & 15) == 0;

    if ((n & 3) == 0 && shift >= 2 && aligned16) {
        // float4 fast path. swapbit and its >>1 stay above f4 granularity
        // because shift>=2 keeps swapbit_f>=16384 (>> 2 >> 1 still >= 2048).
        int n4 = n >> 2;
        int swapbit4 = swapbit_f >> 2;               // same bit, f4-index space
        int blocks = (n4 + THREADS - 1) / THREADS;   // 512 for n=524288
        cnot_perm_f4<<<blocks, THREADS>>>((const float4*)xf, (float4*)outf,
                                          swapbit4, n4);
    } else {
        int blocks = (n + THREADS - 1) / THREADS;
        cnot_perm_f1<<<blocks, THREADS>>>(xf, outf, swapbit_f, n);
    }
}

// round 15
// speedup vs baseline: 1.4931x; 1.4375x over previous
#include <cuda_runtime.h>
#include <cstdint>

// CNOT (13 qubits, control bit12, target bit11 of the state row) as a pure
// permutation copy: out[i,:] = x[i ^ ((i&4096)>>1), :]. U never read.
//
// Established (R6/R10 passes, rel_err=0): x = 524288 floats, 64 per state
// row; at flat float4-index granularity src = idx ^ ((idx & swapbit4) >> 1).
//
// R10 ncu: DRAM 5.9%, issue 5.9% -> latency/ramp floor, not BW. This round:
// 4 independent float4 accesses per thread (MLP=4), grid 512 -> 128 CTAs,
// segmented mapping so each quarter-segment stays perfectly coalesced.

__global__ void __launch_bounds__(256) cnot_perm_f4x4(
    const float4* __restrict__ x, float4* __restrict__ out,
    int swapbit, int seg)   // seg = n4/4
{
    int t = blockIdx.x * blockDim.x + threadIdx.x;
    if (t >= seg) return;

    int i0 = t;
    int i1 = t + seg;
    int i2 = t + 2 * seg;
    int i3 = t + 3 * seg;

    // 4 independent loads issued back-to-back (MLP=4), then 4 stores.
    float4 v0 = x[i0 ^ ((i0 & swapbit) >> 1)];
    float4 v1 = x[i1 ^ ((i1 & swapbit) >> 1)];
    float4 v2 = x[i2 ^ ((i2 & swapbit) >> 1)];
    float4 v3 = x[i3 ^ ((i3 & swapbit) >> 1)];

    out[i0] = v0;
    out[i1] = v1;
    out[i2] = v2;
    out[i3] = v3;
}

__global__ void __launch_bounds__(256) cnot_perm_f1(
    const float* __restrict__ x, float* __restrict__ out,
    int swapbit, int n)
{
    int idx = blockIdx.x * blockDim.x + threadIdx.x;
    if (idx >= n) return;
    out[idx] = x[idx ^ ((idx & swapbit) >> 1)];
}

static constexpr int D_ROWS = 8192;

static inline int ilog2i(int v) { int s = 0; while ((1 << s) < v) s++; return s; }

extern "C" void kernel_launch(void* const* d_in, const int* in_sizes, int n_in,
                              void* d_out, int out_size)
{
    // x = smallest input buffer (U is ~128x larger under any lowering).
    int xi = 0;
    for (int i = 1; i < n_in; i++)
        if (in_sizes[i] < in_sizes[xi]) xi = i;

    int n = out_size < in_sizes[xi] ? out_size : in_sizes[xi];
    int fpr = n / D_ROWS;                 // floats per state row (R6: 64)
    if (fpr < 1) fpr = 1;
    int shift = ilog2i(fpr);
    n = D_ROWS << shift;                  // exact multiple of row count

    int swapbit_f = 4096 << shift;        // control bit in flat float index

    constexpr int THREADS = 256;
    const float* xf = (const float*)d_in[xi];
    float* outf = (float*)d_out;

    bool aligned16 = ((((uintptr_t)xf) | ((uintptr_t)outf)) & 15) == 0;

    // Fast path: float4 x4 per thread. Requires swap granularity to survive
    // the f4 view (shift>=2 keeps swapbit4>>1 >= 2048) and n4 % 4 == 0.
    if ((n & 15) == 0 && shift >= 2 && aligned16) {
        int n4 = n >> 2;                          // 131072
        int swapbit4 = swapbit_f >> 2;            // same bit, f4-index space
        int seg = n4 >> 2;                        // 32768 threads
        int blocks = (seg + THREADS - 1) / THREADS;  // 128
        cnot_perm_f4x4<<<blocks, THREADS>>>((const float4*)xf, (float4*)outf,
                                            swapbit4, seg);
    } else {
        int blocks = (n + THREADS - 1) / THREADS;
        cnot_perm_f1<<<blocks, THREADS>>>(xf, outf, swapbit_f, n);
    }
}